// round 8
// baseline (speedup 1.0000x reference)
#include <cuda_runtime.h>

#define S 2048
#define D 64
#define BH 32
#define SCALE 0.125f   // 1/sqrt(64)

// ---------------------------------------------------------------------------
// K1: raw masked scores  attn[bh, q, k] = (q . k) / 8  for k<=q, else 0
// Tile: 128 (q) x 64 (k), 256 threads, 8x4 per thread, D chunked by 32.
// ---------------------------------------------------------------------------
__global__ __launch_bounds__(256) void k_scores(const float* __restrict__ qg,
                                                const float* __restrict__ kg,
                                                float* __restrict__ attn)
{
    const int kt = blockIdx.x;          // 0..31  (k in 64-wide tiles)
    const int qt = blockIdx.y;          // 0..15  (q in 128-wide tiles)
    const int bh = blockIdx.z;          // 0..31
    const int q0 = qt * 128;
    const int k0 = kt * 64;

    float* __restrict__ ab = attn + (size_t)bh * S * S;
    const int tid = threadIdx.x;

    // Tiles entirely above the diagonal: write zeros, done.
    if (k0 > q0 + 127) {
        const float4 z = make_float4(0.f, 0.f, 0.f, 0.f);
        #pragma unroll
        for (int i = 0; i < 8; i++) {
            int f4  = tid + i * 256;          // 2048 float4s = 128x64 floats
            int row = f4 >> 4;                // 16 float4 per 64-col row
            int c4  = f4 & 15;
            *reinterpret_cast<float4*>(&ab[(size_t)(q0 + row) * S + k0 + c4 * 4]) = z;
        }
        return;
    }

    const float* __restrict__ qb = qg + (size_t)bh * S * D;
    const float* __restrict__ kb = kg + (size_t)bh * S * D;

    __shared__ float Qs[128][33];   // pad 33: conflict-free a-loads
    __shared__ float Ks[64][33];    // pad 33 + interleaved c-map: conflict-free b-loads

    const int tx = tid & 15;        // 0..15 -> cols c = tx + 16*j
    const int ty = tid >> 4;        // 0..15 -> rows r = 8*ty + i
    const int r0 = ty * 8;

    float acc[8][4];
    #pragma unroll
    for (int i = 0; i < 8; i++)
        #pragma unroll
        for (int j = 0; j < 4; j++) acc[i][j] = 0.f;

    #pragma unroll
    for (int dc = 0; dc < 2; dc++) {
        const int d0 = dc * 32;
        // load Q tile: 128 x 32  (1024 float4, 4 per thread), scalar STS (padded rows)
        #pragma unroll
        for (int i = 0; i < 4; i++) {
            int f4  = tid + i * 256;
            int row = f4 >> 3;              // 8 float4 per 32-col row
            int d4  = (f4 & 7) * 4;
            float4 v = *reinterpret_cast<const float4*>(&qb[(size_t)(q0 + row) * D + d0 + d4]);
            Qs[row][d4 + 0] = v.x; Qs[row][d4 + 1] = v.y;
            Qs[row][d4 + 2] = v.z; Qs[row][d4 + 3] = v.w;
        }
        // load K tile: 64 x 32  (512 float4, 2 per thread)
        #pragma unroll
        for (int i = 0; i < 2; i++) {
            int f4  = tid + i * 256;
            int row = f4 >> 3;
            int d4  = (f4 & 7) * 4;
            float4 v = *reinterpret_cast<const float4*>(&kb[(size_t)(k0 + row) * D + d0 + d4]);
            Ks[row][d4 + 0] = v.x; Ks[row][d4 + 1] = v.y;
            Ks[row][d4 + 2] = v.z; Ks[row][d4 + 3] = v.w;
        }
        __syncthreads();

        #pragma unroll 8
        for (int kk = 0; kk < 32; kk++) {
            float a[8], b[4];
            #pragma unroll
            for (int i = 0; i < 8; i++) a[i] = Qs[r0 + i][kk];
            #pragma unroll
            for (int j = 0; j < 4; j++) b[j] = Ks[tx + 16 * j][kk];
            #pragma unroll
            for (int i = 0; i < 8; i++)
                #pragma unroll
                for (int j = 0; j < 4; j++)
                    acc[i][j] = fmaf(a[i], b[j], acc[i][j]);
        }
        __syncthreads();
    }

    // write raw scores with causal mask (masked = 0.0)
    #pragma unroll
    for (int i = 0; i < 8; i++) {
        const int gq = q0 + r0 + i;
        #pragma unroll
        for (int j = 0; j < 4; j++) {
            const int gk = k0 + tx + 16 * j;
            ab[(size_t)gq * S + gk] = (gk <= gq) ? acc[i][j] * SCALE : 0.f;
        }
    }
}

// ---------------------------------------------------------------------------
// K2: in-place row softmax over attn[bh, q, 0..q]  (entries > q stay 0)
// One block (128 threads) per row; row cached in smem.
// ---------------------------------------------------------------------------
__global__ __launch_bounds__(128) void k_softmax(float* __restrict__ attn)
{
    const int row = blockIdx.x;            // 0..65535
    const int bh  = row >> 11;
    const int qy  = row & 2047;
    float* __restrict__ a = attn + (size_t)bh * S * S + (size_t)qy * S;
    const int len = qy + 1;

    __shared__ float buf[2048];
    __shared__ float red[4];
    const int tid  = threadIdx.x;
    const int lane = tid & 31;
    const int wrp  = tid >> 5;

    float m = -1e30f;
    for (int i = tid; i < len; i += 128) {
        float v = a[i];
        buf[i] = v;
        m = fmaxf(m, v);
    }
    #pragma unroll
    for (int o = 16; o; o >>= 1) m = fmaxf(m, __shfl_xor_sync(0xffffffffu, m, o));
    if (lane == 0) red[wrp] = m;
    __syncthreads();
    m = fmaxf(fmaxf(red[0], red[1]), fmaxf(red[2], red[3]));

    float s = 0.f;
    for (int i = tid; i < len; i += 128) {
        float e = __expf(buf[i] - m);
        buf[i] = e;
        s += e;
    }
    #pragma unroll
    for (int o = 16; o; o >>= 1) s += __shfl_xor_sync(0xffffffffu, s, o);
    __syncthreads();                        // everyone done reading red for max
    if (lane == 0) red[wrp] = s;
    __syncthreads();
    s = red[0] + red[1] + red[2] + red[3];
    const float inv = 1.f / s;

    for (int i = tid; i < len; i += 128) a[i] = buf[i] * inv;
}

// ---------------------------------------------------------------------------
// K3: out[bh, q, d] = sum_k attn[bh, q, k] * v[bh, k, d]
// Tile: 128 (q) x 64 (d), 256 threads, 8x4 per thread, k chunked by 32.
// attn zeros above the diagonal make the diagonal tile mask-free.
// ---------------------------------------------------------------------------
__global__ __launch_bounds__(256) void k_av(const float* __restrict__ attn,
                                            const float* __restrict__ vg,
                                            float* __restrict__ outg)
{
    const int qt = 15 - (int)blockIdx.x;   // descending work order for balance
    const int bh = blockIdx.y;
    const int q0 = qt * 128;

    const float* __restrict__ ab = attn + (size_t)bh * S * S;
    const float* __restrict__ vb = vg   + (size_t)bh * S * D;
    float* __restrict__ ob       = outg + (size_t)bh * S * D;

    __shared__ float As[128][33];   // pad: conflict-free a-loads
    __shared__ float Vs[32][64];    // natural layout: conflict-free float4 b-loads

    const int tid = threadIdx.x;
    const int tx  = tid & 15;       // cols c0 = 4*tx (float4)
    const int ty  = tid >> 4;       // rows r0 = 8*ty
    const int r0  = ty * 8;
    const int c0  = tx * 4;

    float acc[8][4];
    #pragma unroll
    for (int i = 0; i < 8; i++)
        #pragma unroll
        for (int j = 0; j < 4; j++) acc[i][j] = 0.f;

    const int nch = (qt + 1) * 4;   // 32-wide k-chunks covering k <= q0+127

    for (int ch = 0; ch < nch; ch++) {
        const int kb = ch * 32;
        // load attn tile 128 x 32 (1024 float4, 4 per thread), scalar STS
        #pragma unroll
        for (int i = 0; i < 4; i++) {
            int f4  = tid + i * 256;
            int row = f4 >> 3;
            int k4  = (f4 & 7) * 4;
            float4 v = *reinterpret_cast<const float4*>(&ab[(size_t)(q0 + row) * S + kb + k4]);
            As[row][k4 + 0] = v.x; As[row][k4 + 1] = v.y;
            As[row][k4 + 2] = v.z; As[row][k4 + 3] = v.w;
        }
        // load V tile 32 x 64 (512 float4, 2 per thread), float4 STS
        #pragma unroll
        for (int i = 0; i < 2; i++) {
            int f4  = tid + i * 256;
            int row = f4 >> 4;              // 16 float4 per 64-col row
            int c4  = (f4 & 15) * 4;
            float4 v = *reinterpret_cast<const float4*>(&vb[(size_t)(kb + row) * D + c4]);
            *reinterpret_cast<float4*>(&Vs[row][c4]) = v;
        }
        __syncthreads();

        #pragma unroll 8
        for (int kk = 0; kk < 32; kk++) {
            float a[8];
            #pragma unroll
            for (int i = 0; i < 8; i++) a[i] = As[r0 + i][kk];
            float4 b = *reinterpret_cast<const float4*>(&Vs[kk][c0]);
            #pragma unroll
            for (int i = 0; i < 8; i++) {
                acc[i][0] = fmaf(a[i], b.x, acc[i][0]);
                acc[i][1] = fmaf(a[i], b.y, acc[i][1]);
                acc[i][2] = fmaf(a[i], b.z, acc[i][2]);
                acc[i][3] = fmaf(a[i], b.w, acc[i][3]);
            }
        }
        __syncthreads();
    }

    #pragma unroll
    for (int i = 0; i < 8; i++) {
        float4 o = make_float4(acc[i][0], acc[i][1], acc[i][2], acc[i][3]);
        *reinterpret_cast<float4*>(&ob[(size_t)(q0 + r0 + i) * D + c0]) = o;
    }
}

// ---------------------------------------------------------------------------
// launch: d_in = { q, k, v, mask } ; d_out = [ out (B*H*S*D) | attn (B*H*S*S) ]
// ---------------------------------------------------------------------------
extern "C" void kernel_launch(void* const* d_in, const int* in_sizes, int n_in,
                              void* d_out, int out_size)
{
    const float* q = (const float*)d_in[0];
    const float* k = (const float*)d_in[1];
    const float* v = (const float*)d_in[2];
    // d_in[3] = mask (unused: causal mask is structural)

    float* out  = (float*)d_out;
    float* attn = out + (size_t)BH * S * D;   // tuple order: (out, attn)

    k_scores <<<dim3(32, 16, BH), 256>>>(q, k, attn);
    k_softmax<<<BH * S, 128>>>(attn);
    k_av     <<<dim3(16, BH), 256>>>(attn, v, out);
}

// round 11
// speedup vs baseline: 1.6764x; 1.6764x over previous
#include <cuda_runtime.h>
#include <cuda_bf16.h>
#include <cstdint>

#define S 2048
#define D 64
#define BH 32
#define SCALE 0.125f   // 1/sqrt(64)

#define TS  72   // bf16 stride for Q/K/P smem tiles (144 B/row, 36 words)
#define TSW 36   // TS in 32-bit words
#define VST 70   // bf16 stride for transposed V tile (140 B/row, 35 words)

// ---------------------------------------------------------------------------
// mma.sync bf16 (sm_80 baseline PTX -> compiles at compute_103, runs on HMMA)
// ---------------------------------------------------------------------------
__device__ __forceinline__ void mma_bf16(float* c, const uint32_t* a,
                                         uint32_t b0, uint32_t b1) {
    asm volatile(
        "mma.sync.aligned.m16n8k16.row.col.f32.bf16.bf16.f32 "
        "{%0,%1,%2,%3}, {%4,%5,%6,%7}, {%8,%9}, {%0,%1,%2,%3};"
        : "+f"(c[0]), "+f"(c[1]), "+f"(c[2]), "+f"(c[3])
        : "r"(a[0]), "r"(a[1]), "r"(a[2]), "r"(a[3]), "r"(b0), "r"(b1));
}

// split-bf16 of 2 floats: h = packed {bf16(a),bf16(b)}, l = packed residuals
__device__ __forceinline__ void cvt2(float a, float b, uint32_t& h, uint32_t& l) {
    __nv_bfloat162 h2 = __floats2bfloat162_rn(a, b);
    float ra = a - __bfloat162float(h2.x);
    float rb = b - __bfloat162float(h2.y);
    __nv_bfloat162 l2 = __floats2bfloat162_rn(ra, rb);
    h = *reinterpret_cast<uint32_t*>(&h2);
    l = *reinterpret_cast<uint32_t*>(&l2);
}

__device__ __forceinline__ void cvt1(float x, uint16_t& h, uint16_t& l) {
    __nv_bfloat16 hb = __float2bfloat16(x);
    __nv_bfloat16 lb = __float2bfloat16(x - __bfloat162float(hb));
    h = *reinterpret_cast<uint16_t*>(&hb);
    l = *reinterpret_cast<uint16_t*>(&lb);
}

// Load a 128x64 f32 tile (row stride ld) into hi/lo bf16 smem tiles (stride TS).
// 256 threads, 8 contiguous floats per thread per iter; STS.128 conflict-free.
__device__ __forceinline__ void load_tile_128x64(const float* __restrict__ g,
                                                 size_t ld, uint16_t* hi,
                                                 uint16_t* lo, int tid) {
    #pragma unroll
    for (int j = 0; j < 4; j++) {
        int gidx = tid + j * 256;          // 1024 granules of 8 floats
        int row  = gidx >> 3;
        int i    = gidx & 7;
        const float* src = g + (size_t)row * ld + i * 8;
        float4 x = *reinterpret_cast<const float4*>(src);
        float4 y = *reinterpret_cast<const float4*>(src + 4);
        uint32_t h0, h1, h2, h3, l0, l1, l2, l3;
        cvt2(x.x, x.y, h0, l0);
        cvt2(x.z, x.w, h1, l1);
        cvt2(y.x, y.y, h2, l2);
        cvt2(y.z, y.w, h3, l3);
        int off = row * TS + i * 8;        // byte = row*144 + i*16 (16B aligned)
        *reinterpret_cast<uint4*>(hi + off) = make_uint4(h0, h1, h2, h3);
        *reinterpret_cast<uint4*>(lo + off) = make_uint4(l0, l1, l2, l3);
    }
}

// ===========================================================================
// K1: scores via split-bf16 mma. Tile 128(q) x 128(k), Kdim=64 (4 ksteps).
// attn[bh,q,k] = (q.k)/8 for k<=q else 0
// ===========================================================================
#define K1_SMEM (4 * 128 * TS * 2)   // Qhi,Qlo,Khi,Klo = 73728 B

__global__ __launch_bounds__(256) void k_scores_mma(const float* __restrict__ qg,
                                                    const float* __restrict__ kg,
                                                    float* __restrict__ attn)
{
    const int kt = blockIdx.x;     // 0..15
    const int qt = blockIdx.y;     // 0..15
    const int bh = blockIdx.z;
    const int q0 = qt * 128;
    const int k0 = kt * 128;
    const int tid = threadIdx.x;

    float* __restrict__ ab = attn + (size_t)bh * S * S;

    if (kt > qt) {                 // strictly upper tiles: zero-fill
        const float4 z = make_float4(0.f, 0.f, 0.f, 0.f);
        #pragma unroll
        for (int i = 0; i < 16; i++) {
            int f4  = tid + i * 256;          // 4096 float4 = 128x128
            int row = f4 >> 5;
            int c   = (f4 & 31) * 4;
            *reinterpret_cast<float4*>(&ab[(size_t)(q0 + row) * S + k0 + c]) = z;
        }
        return;
    }

    extern __shared__ uint16_t sm[];
    uint16_t* Qhi = sm;
    uint16_t* Qlo = sm + 128 * TS;
    uint16_t* Khi = sm + 2 * 128 * TS;
    uint16_t* Klo = sm + 3 * 128 * TS;

    load_tile_128x64(qg + ((size_t)bh * S + q0) * D, D, Qhi, Qlo, tid);
    load_tile_128x64(kg + ((size_t)bh * S + k0) * D, D, Khi, Klo, tid);
    __syncthreads();

    const int wid  = tid >> 5;
    const int lane = tid & 31;
    const int g    = lane >> 2;    // groupID 0..7
    const int tg   = lane & 3;     // thread-in-group 0..3
    const int wq   = wid >> 1;     // 0..3 -> q offset 32*wq
    const int wk   = wid & 1;      // 0..1 -> k offset 64*wk

    float acc[2][8][4];
    #pragma unroll
    for (int m = 0; m < 2; m++)
        #pragma unroll
        for (int n = 0; n < 8; n++)
            #pragma unroll
            for (int e = 0; e < 4; e++) acc[m][n][e] = 0.f;

    const uint32_t* qh = reinterpret_cast<const uint32_t*>(Qhi);
    const uint32_t* ql = reinterpret_cast<const uint32_t*>(Qlo);
    const uint32_t* kh = reinterpret_cast<const uint32_t*>(Khi);
    const uint32_t* kl = reinterpret_cast<const uint32_t*>(Klo);

    #pragma unroll
    for (int ks = 0; ks < 4; ks++) {
        uint32_t Ahi[2][4], Alo[2][4];
        #pragma unroll
        for (int m = 0; m < 2; m++) {
            int base = (wq * 32 + m * 16 + g) * TSW + tg + ks * 8;
            Ahi[m][0] = qh[base];               Ahi[m][1] = qh[base + 8 * TSW];
            Ahi[m][2] = qh[base + 4];           Ahi[m][3] = qh[base + 8 * TSW + 4];
            Alo[m][0] = ql[base];               Alo[m][1] = ql[base + 8 * TSW];
            Alo[m][2] = ql[base + 4];           Alo[m][3] = ql[base + 8 * TSW + 4];
        }
        #pragma unroll
        for (int n = 0; n < 8; n++) {
            int base = (wk * 64 + n * 8 + g) * TSW + tg + ks * 8;
            uint32_t bh0 = kh[base], bh1 = kh[base + 4];
            uint32_t bl0 = kl[base], bl1 = kl[base + 4];
            mma_bf16(acc[0][n], Ahi[0], bh0, bh1);
            mma_bf16(acc[1][n], Ahi[1], bh0, bh1);
            mma_bf16(acc[0][n], Ahi[0], bl0, bl1);
            mma_bf16(acc[1][n], Ahi[1], bl0, bl1);
            mma_bf16(acc[0][n], Alo[0], bh0, bh1);
            mma_bf16(acc[1][n], Alo[1], bh0, bh1);
        }
    }

    const bool diag = (kt == qt);
    #pragma unroll
    for (int m = 0; m < 2; m++) {
        int gq = q0 + wq * 32 + m * 16 + g;
        #pragma unroll
        for (int n = 0; n < 8; n++) {
            int gk = k0 + wk * 64 + n * 8 + tg * 2;
            float2 v0 = make_float2(acc[m][n][0] * SCALE, acc[m][n][1] * SCALE);
            float2 v1 = make_float2(acc[m][n][2] * SCALE, acc[m][n][3] * SCALE);
            if (diag) {
                if (gk     > gq)     v0.x = 0.f;
                if (gk + 1 > gq)     v0.y = 0.f;
                if (gk     > gq + 8) v1.x = 0.f;
                if (gk + 1 > gq + 8) v1.y = 0.f;
            }
            *reinterpret_cast<float2*>(&ab[(size_t)gq * S + gk])       = v0;
            *reinterpret_cast<float2*>(&ab[(size_t)(gq + 8) * S + gk]) = v1;
        }
    }
}

// ===========================================================================
// K2: in-place row softmax over attn[bh, q, 0..q]
// ===========================================================================
__global__ __launch_bounds__(128) void k_softmax(float* __restrict__ attn)
{
    const int row = blockIdx.x;
    const int bh  = row >> 11;
    const int qy  = row & 2047;
    float* __restrict__ a = attn + (size_t)bh * S * S + (size_t)qy * S;
    const int len = qy + 1;

    __shared__ float buf[2048];
    __shared__ float red[4];
    const int tid  = threadIdx.x;
    const int lane = tid & 31;
    const int wrp  = tid >> 5;

    float m = -1e30f;
    for (int i = tid; i < len; i += 128) {
        float v = a[i];
        buf[i] = v;
        m = fmaxf(m, v);
    }
    #pragma unroll
    for (int o = 16; o; o >>= 1) m = fmaxf(m, __shfl_xor_sync(0xffffffffu, m, o));
    if (lane == 0) red[wrp] = m;
    __syncthreads();
    m = fmaxf(fmaxf(red[0], red[1]), fmaxf(red[2], red[3]));

    float s = 0.f;
    for (int i = tid; i < len; i += 128) {
        float e = __expf(buf[i] - m);
        buf[i] = e;
        s += e;
    }
    #pragma unroll
    for (int o = 16; o; o >>= 1) s += __shfl_xor_sync(0xffffffffu, s, o);
    __syncthreads();
    if (lane == 0) red[wrp] = s;
    __syncthreads();
    s = red[0] + red[1] + red[2] + red[3];
    const float inv = 1.f / s;

    for (int i = tid; i < len; i += 128) a[i] = buf[i] * inv;
}

// ===========================================================================
// K3: out = attn @ V via split-bf16 mma. Tile 128(q) x 64(d), k chunks of 64.
// ===========================================================================
#define K3_SMEM (2 * 128 * TS * 2 + 2 * 64 * VST * 2)   // 54784 B

__global__ __launch_bounds__(256) void k_av_mma(const float* __restrict__ attn,
                                                const float* __restrict__ vg,
                                                float* __restrict__ outg)
{
    const int qt = 15 - (int)blockIdx.x;    // descending work order
    const int bh = blockIdx.y;
    const int q0 = qt * 128;
    const int tid = threadIdx.x;

    const float* __restrict__ ab = attn + (size_t)bh * S * S;
    const float* __restrict__ vb = vg   + (size_t)bh * S * D;
    float* __restrict__ ob       = outg + (size_t)bh * S * D;

    extern __shared__ uint16_t sm[];
    uint16_t* Phi = sm;
    uint16_t* Plo = sm + 128 * TS;
    uint16_t* Vhi = sm + 2 * 128 * TS;          // transposed: Vhi[d*VST + k]
    uint16_t* Vlo = Vhi + 64 * VST;

    const int wid  = tid >> 5;
    const int lane = tid & 31;
    const int g    = lane >> 2;
    const int tg   = lane & 3;
    const int wq   = wid >> 1;    // 0..3 -> q offset 32*wq
    const int wd   = wid & 1;     // 0..1 -> d offset 32*wd

    float acc[2][4][4];
    #pragma unroll
    for (int m = 0; m < 2; m++)
        #pragma unroll
        for (int n = 0; n < 4; n++)
            #pragma unroll
            for (int e = 0; e < 4; e++) acc[m][n][e] = 0.f;

    const uint32_t* ph = reinterpret_cast<const uint32_t*>(Phi);
    const uint32_t* pl = reinterpret_cast<const uint32_t*>(Plo);
    const uint32_t* vh = reinterpret_cast<const uint32_t*>(Vhi);
    const uint32_t* vl = reinterpret_cast<const uint32_t*>(Vlo);

    const int vd = tid & 63;      // this thread's d for V transpose
    const int vk0 = (tid >> 6) * 16;

    const int nch = (qt + 1) * 2;           // 64-wide k chunks
    for (int ch = 0; ch < nch; ch++) {
        const int kb = ch * 64;
        // P tile 128x64 from attn (row stride S)
        load_tile_128x64(ab + (size_t)q0 * S + kb, S, Phi, Plo, tid);
        // V tile 64x64, stored transposed (conflict-free: banks 3d / 3g+tg)
        #pragma unroll
        for (int i = 0; i < 16; i++) {
            int k = vk0 + i;
            float x = vb[(size_t)(kb + k) * D + vd];
            uint16_t h, l;
            cvt1(x, h, l);
            Vhi[vd * VST + k] = h;
            Vlo[vd * VST + k] = l;
        }
        __syncthreads();

        #pragma unroll
        for (int ks = 0; ks < 4; ks++) {
            uint32_t Ahi[2][4], Alo[2][4];
            #pragma unroll
            for (int m = 0; m < 2; m++) {
                int base = (wq * 32 + m * 16 + g) * TSW + tg + ks * 8;
                Ahi[m][0] = ph[base];           Ahi[m][1] = ph[base + 8 * TSW];
                Ahi[m][2] = ph[base + 4];       Ahi[m][3] = ph[base + 8 * TSW + 4];
                Alo[m][0] = pl[base];           Alo[m][1] = pl[base + 8 * TSW];
                Alo[m][2] = pl[base + 4];       Alo[m][3] = pl[base + 8 * TSW + 4];
            }
            #pragma unroll
            for (int n = 0; n < 4; n++) {
                int base = (wd * 32 + n * 8 + g) * 35 + tg + ks * 8;  // 35 words/row
                uint32_t bh0 = vh[base], bh1 = vh[base + 4];
                uint32_t bl0 = vl[base], bl1 = vl[base + 4];
                mma_bf16(acc[0][n], Ahi[0], bh0, bh1);
                mma_bf16(acc[1][n], Ahi[1], bh0, bh1);
                mma_bf16(acc[0][n], Ahi[0], bl0, bl1);
                mma_bf16(acc[1][n], Ahi[1], bl0, bl1);
                mma_bf16(acc[0][n], Alo[0], bh0, bh1);
                mma_bf16(acc[1][n], Alo[1], bh0, bh1);
            }
        }
        __syncthreads();
    }

    #pragma unroll
    for (int m = 0; m < 2; m++) {
        int gq = q0 + wq * 32 + m * 16 + g;
        #pragma unroll
        for (int n = 0; n < 4; n++) {
            int gd = wd * 32 + n * 8 + tg * 2;
            *reinterpret_cast<float2*>(&ob[(size_t)gq * D + gd]) =
                make_float2(acc[m][n][0], acc[m][n][1]);
            *reinterpret_cast<float2*>(&ob[(size_t)(gq + 8) * D + gd]) =
                make_float2(acc[m][n][2], acc[m][n][3]);
        }
    }
}

// ===========================================================================
// launch: d_in = { q, k, v, mask } ; d_out = [ out | attn ]
// ===========================================================================
extern "C" void kernel_launch(void* const* d_in, const int* in_sizes, int n_in,
                              void* d_out, int out_size)
{
    const float* q = (const float*)d_in[0];
    const float* k = (const float*)d_in[1];
    const float* v = (const float*)d_in[2];

    float* out  = (float*)d_out;
    float* attn = out + (size_t)BH * S * D;

    static bool configured = false;
    if (!configured) {
        cudaFuncSetAttribute(k_scores_mma, cudaFuncAttributeMaxDynamicSharedMemorySize, K1_SMEM);
        cudaFuncSetAttribute(k_av_mma,     cudaFuncAttributeMaxDynamicSharedMemorySize, K3_SMEM);
        configured = true;
    }

    k_scores_mma<<<dim3(16, 16, BH), 256, K1_SMEM>>>(q, k, attn);
    k_softmax   <<<BH * S, 128>>>(attn);
    k_av_mma    <<<dim3(16, BH), 256, K3_SMEM>>>(attn, v, out);
}

// round 12
// speedup vs baseline: 1.7867x; 1.0658x over previous
#include <cuda_runtime.h>
#include <cuda_bf16.h>
#include <cstdint>

#define S 2048
#define D 64
#define BH 32
#define SCALE 0.125f   // 1/sqrt(64)

#define TS   72        // bf16 row stride for all smem tiles (144 B, 16B-aligned)
#define ROWB 144       // TS * 2 bytes
#define MROWB 2304     // 16 * ROWB : one 16-row tile step

// ---------------------------------------------------------------------------
// mma.sync bf16 + ldmatrix helpers (sm_80 baseline PTX, compiles at compute_103)
// ---------------------------------------------------------------------------
__device__ __forceinline__ void mma_bf16(float* c, const uint32_t* a,
                                         uint32_t b0, uint32_t b1) {
    asm volatile(
        "mma.sync.aligned.m16n8k16.row.col.f32.bf16.bf16.f32 "
        "{%0,%1,%2,%3}, {%4,%5,%6,%7}, {%8,%9}, {%0,%1,%2,%3};"
        : "+f"(c[0]), "+f"(c[1]), "+f"(c[2]), "+f"(c[3])
        : "r"(a[0]), "r"(a[1]), "r"(a[2]), "r"(a[3]), "r"(b0), "r"(b1));
}

__device__ __forceinline__ uint32_t smem_u32(const void* p) {
    uint32_t a;
    asm("{ .reg .u64 t; cvta.to.shared.u64 t, %1; cvt.u32.u64 %0, t; }"
        : "=r"(a) : "l"(p));
    return a;
}

__device__ __forceinline__ void ldsm4(uint32_t* r, uint32_t a) {
    asm volatile("ldmatrix.sync.aligned.m8n8.x4.shared.b16 {%0,%1,%2,%3}, [%4];"
                 : "=r"(r[0]), "=r"(r[1]), "=r"(r[2]), "=r"(r[3]) : "r"(a));
}
__device__ __forceinline__ void ldsm4t(uint32_t* r, uint32_t a) {
    asm volatile("ldmatrix.sync.aligned.m8n8.x4.trans.shared.b16 {%0,%1,%2,%3}, [%4];"
                 : "=r"(r[0]), "=r"(r[1]), "=r"(r[2]), "=r"(r[3]) : "r"(a));
}

// split-bf16 of 2 floats
__device__ __forceinline__ void cvt2(float a, float b, uint32_t& h, uint32_t& l) {
    __nv_bfloat162 h2 = __floats2bfloat162_rn(a, b);
    float ra = a - __bfloat162float(h2.x);
    float rb = b - __bfloat162float(h2.y);
    __nv_bfloat162 l2 = __floats2bfloat162_rn(ra, rb);
    h = *reinterpret_cast<uint32_t*>(&h2);
    l = *reinterpret_cast<uint32_t*>(&l2);
}

// Load rows x 64 f32 tile (row stride ld) into hi/lo bf16 smem (stride TS).
// 8 contiguous floats per thread per granule; LDG.128 + STS.128, conflict-free.
template<int ITERS>
__device__ __forceinline__ void load_tile_64w(const float* __restrict__ g,
                                              size_t ld, uint16_t* hi,
                                              uint16_t* lo, int tid) {
    #pragma unroll
    for (int j = 0; j < ITERS; j++) {
        int gidx = tid + j * 256;
        int row  = gidx >> 3;
        int i    = gidx & 7;
        const float* src = g + (size_t)row * ld + i * 8;
        float4 x = *reinterpret_cast<const float4*>(src);
        float4 y = *reinterpret_cast<const float4*>(src + 4);
        uint32_t h0, h1, h2, h3, l0, l1, l2, l3;
        cvt2(x.x, x.y, h0, l0);
        cvt2(x.z, x.w, h1, l1);
        cvt2(y.x, y.y, h2, l2);
        cvt2(y.z, y.w, h3, l3);
        int off = row * TS + i * 8;
        *reinterpret_cast<uint4*>(hi + off) = make_uint4(h0, h1, h2, h3);
        *reinterpret_cast<uint4*>(lo + off) = make_uint4(l0, l1, l2, l3);
    }
}

// ===========================================================================
// K1: scores via split-bf16 mma + ldmatrix. Tile 128(q) x 128(k), 4 ksteps.
// attn[bh,q,k] = (q.k)/8 for k<=q else 0
// ===========================================================================
#define K1_SMEM (4 * 128 * TS * 2)   // 73728 B

__global__ __launch_bounds__(256) void k_scores_mma(const float* __restrict__ qg,
                                                    const float* __restrict__ kg,
                                                    float* __restrict__ attn)
{
    const int kt = blockIdx.x;
    const int qt = blockIdx.y;
    const int bh = blockIdx.z;
    const int q0 = qt * 128;
    const int k0 = kt * 128;
    const int tid = threadIdx.x;

    float* __restrict__ ab = attn + (size_t)bh * S * S;

    if (kt > qt) {                 // strictly upper tiles: zero-fill
        const float4 z = make_float4(0.f, 0.f, 0.f, 0.f);
        #pragma unroll
        for (int i = 0; i < 16; i++) {
            int f4  = tid + i * 256;
            int row = f4 >> 5;
            int c   = (f4 & 31) * 4;
            *reinterpret_cast<float4*>(&ab[(size_t)(q0 + row) * S + k0 + c]) = z;
        }
        return;
    }

    extern __shared__ uint16_t sm[];
    uint16_t* Qhi = sm;
    uint16_t* Qlo = sm + 128 * TS;
    uint16_t* Khi = sm + 2 * 128 * TS;
    uint16_t* Klo = sm + 3 * 128 * TS;

    load_tile_64w<4>(qg + ((size_t)bh * S + q0) * D, D, Qhi, Qlo, tid);
    load_tile_64w<4>(kg + ((size_t)bh * S + k0) * D, D, Khi, Klo, tid);
    __syncthreads();

    const int wid  = tid >> 5;
    const int lane = tid & 31;
    const int g    = lane >> 2;
    const int tg   = lane & 3;
    const int wq   = wid >> 1;     // q offset 32*wq
    const int wk   = wid & 1;      // k offset 64*wk
    const int mid  = lane >> 3;    // ldmatrix matrix id
    const int r7   = lane & 7;

    // ldmatrix base addresses (lane-dependent)
    const uint32_t aOff = (uint32_t)(wq * 32 + (mid & 1) * 8 + r7) * ROWB
                        + (uint32_t)(mid >> 1) * 16;
    const uint32_t bOff = (uint32_t)(wk * 64 + (mid >> 1) * 8 + r7) * ROWB
                        + (uint32_t)(mid & 1) * 16;
    const uint32_t aHi = smem_u32(Qhi) + aOff, aLo = smem_u32(Qlo) + aOff;
    const uint32_t bHi = smem_u32(Khi) + bOff, bLo = smem_u32(Klo) + bOff;

    float acc[2][8][4];
    #pragma unroll
    for (int m = 0; m < 2; m++)
        #pragma unroll
        for (int n = 0; n < 8; n++)
            #pragma unroll
            for (int e = 0; e < 4; e++) acc[m][n][e] = 0.f;

    #pragma unroll
    for (int ks = 0; ks < 4; ks++) {
        const uint32_t kb = ks * 32;
        uint32_t Ah[2][4], Al[2][4];
        ldsm4(Ah[0], aHi + kb);
        ldsm4(Ah[1], aHi + MROWB + kb);
        ldsm4(Al[0], aLo + kb);
        ldsm4(Al[1], aLo + MROWB + kb);
        #pragma unroll
        for (int p = 0; p < 4; p++) {
            uint32_t Bh[4], Bl[4];
            ldsm4(Bh, bHi + p * MROWB + kb);
            ldsm4(Bl, bLo + p * MROWB + kb);
            mma_bf16(acc[0][2*p],   Ah[0], Bh[0], Bh[1]);
            mma_bf16(acc[1][2*p],   Ah[1], Bh[0], Bh[1]);
            mma_bf16(acc[0][2*p],   Ah[0], Bl[0], Bl[1]);
            mma_bf16(acc[1][2*p],   Ah[1], Bl[0], Bl[1]);
            mma_bf16(acc[0][2*p],   Al[0], Bh[0], Bh[1]);
            mma_bf16(acc[1][2*p],   Al[1], Bh[0], Bh[1]);
            mma_bf16(acc[0][2*p+1], Ah[0], Bh[2], Bh[3]);
            mma_bf16(acc[1][2*p+1], Ah[1], Bh[2], Bh[3]);
            mma_bf16(acc[0][2*p+1], Ah[0], Bl[2], Bl[3]);
            mma_bf16(acc[1][2*p+1], Ah[1], Bl[2], Bl[3]);
            mma_bf16(acc[0][2*p+1], Al[0], Bh[2], Bh[3]);
            mma_bf16(acc[1][2*p+1], Al[1], Bh[2], Bh[3]);
        }
    }

    const bool diag = (kt == qt);
    #pragma unroll
    for (int m = 0; m < 2; m++) {
        int gq = q0 + wq * 32 + m * 16 + g;
        #pragma unroll
        for (int n = 0; n < 8; n++) {
            int gk = k0 + wk * 64 + n * 8 + tg * 2;
            float2 v0 = make_float2(acc[m][n][0] * SCALE, acc[m][n][1] * SCALE);
            float2 v1 = make_float2(acc[m][n][2] * SCALE, acc[m][n][3] * SCALE);
            if (diag) {
                if (gk     > gq)     v0.x = 0.f;
                if (gk + 1 > gq)     v0.y = 0.f;
                if (gk     > gq + 8) v1.x = 0.f;
                if (gk + 1 > gq + 8) v1.y = 0.f;
            }
            *reinterpret_cast<float2*>(&ab[(size_t)gq * S + gk])       = v0;
            *reinterpret_cast<float2*>(&ab[(size_t)(gq + 8) * S + gk]) = v1;
        }
    }
}

// ===========================================================================
// K2: in-place row softmax over attn[bh, q, 0..q]
// ===========================================================================
__global__ __launch_bounds__(128) void k_softmax(float* __restrict__ attn)
{
    const int row = blockIdx.x;
    const int bh  = row >> 11;
    const int qy  = row & 2047;
    float* __restrict__ a = attn + (size_t)bh * S * S + (size_t)qy * S;
    const int len = qy + 1;

    __shared__ float buf[2048];
    __shared__ float red[4];
    const int tid  = threadIdx.x;
    const int lane = tid & 31;
    const int wrp  = tid >> 5;

    float m = -1e30f;
    for (int i = tid; i < len; i += 128) {
        float v = a[i];
        buf[i] = v;
        m = fmaxf(m, v);
    }
    #pragma unroll
    for (int o = 16; o; o >>= 1) m = fmaxf(m, __shfl_xor_sync(0xffffffffu, m, o));
    if (lane == 0) red[wrp] = m;
    __syncthreads();
    m = fmaxf(fmaxf(red[0], red[1]), fmaxf(red[2], red[3]));

    float s = 0.f;
    for (int i = tid; i < len; i += 128) {
        float e = __expf(buf[i] - m);
        buf[i] = e;
        s += e;
    }
    #pragma unroll
    for (int o = 16; o; o >>= 1) s += __shfl_xor_sync(0xffffffffu, s, o);
    __syncthreads();
    if (lane == 0) red[wrp] = s;
    __syncthreads();
    s = red[0] + red[1] + red[2] + red[3];
    const float inv = 1.f / s;

    for (int i = tid; i < len; i += 128) a[i] = buf[i] * inv;
}

// ===========================================================================
// K3: out = attn @ V via split-bf16 mma + ldmatrix(.trans for V).
// Tile 128(q) x 64(d), k chunks of 64. V kept natural [k][d] in smem.
// ===========================================================================
#define K3_SMEM ((2 * 128 + 2 * 64) * TS * 2)   // 55296 B

__global__ __launch_bounds__(256) void k_av_mma(const float* __restrict__ attn,
                                                const float* __restrict__ vg,
                                                float* __restrict__ outg)
{
    const int qt = 15 - (int)blockIdx.x;
    const int bh = blockIdx.y;
    const int q0 = qt * 128;
    const int tid = threadIdx.x;

    const float* __restrict__ ab = attn + (size_t)bh * S * S;
    const float* __restrict__ vb = vg   + (size_t)bh * S * D;
    float* __restrict__ ob       = outg + (size_t)bh * S * D;

    extern __shared__ uint16_t sm[];
    uint16_t* Phi = sm;
    uint16_t* Plo = sm + 128 * TS;
    uint16_t* Vhi = sm + 2 * 128 * TS;   // natural [k][d], 64 x 64
    uint16_t* Vlo = Vhi + 64 * TS;

    const int wid  = tid >> 5;
    const int lane = tid & 31;
    const int g    = lane >> 2;
    const int tg   = lane & 3;
    const int wq   = wid >> 1;    // q offset 32*wq
    const int wd   = wid & 1;     // d offset 32*wd
    const int mid  = lane >> 3;
    const int r7   = lane & 7;

    const uint32_t aOff = (uint32_t)(wq * 32 + (mid & 1) * 8 + r7) * ROWB
                        + (uint32_t)(mid >> 1) * 16;
    // V (trans): lane addresses k-rows; d column selects 16B chunk
    const uint32_t vOff = (uint32_t)((mid & 1) * 8 + r7) * ROWB
                        + (uint32_t)(wd * 32 + (mid >> 1) * 8) * 2;
    const uint32_t pHi = smem_u32(Phi) + aOff, pLo = smem_u32(Plo) + aOff;
    const uint32_t vHi = smem_u32(Vhi) + vOff, vLo = smem_u32(Vlo) + vOff;

    float acc[2][4][4];
    #pragma unroll
    for (int m = 0; m < 2; m++)
        #pragma unroll
        for (int n = 0; n < 4; n++)
            #pragma unroll
            for (int e = 0; e < 4; e++) acc[m][n][e] = 0.f;

    const int nch = (qt + 1) * 2;           // 64-wide k chunks
    for (int ch = 0; ch < nch; ch++) {
        const int kb = ch * 64;
        load_tile_64w<4>(ab + (size_t)q0 * S + kb, S, Phi, Plo, tid);   // P 128x64
        load_tile_64w<2>(vb + (size_t)kb * D, D, Vhi, Vlo, tid);        // V 64x64
        __syncthreads();

        #pragma unroll
        for (int ks = 0; ks < 4; ks++) {
            const uint32_t akb = ks * 32;       // A: +16 bf16 cols
            const uint32_t vkb = ks * MROWB;    // V: +16 k rows
            uint32_t Ah[2][4], Al[2][4];
            ldsm4(Ah[0], pHi + akb);
            ldsm4(Ah[1], pHi + MROWB + akb);
            ldsm4(Al[0], pLo + akb);
            ldsm4(Al[1], pLo + MROWB + akb);
            #pragma unroll
            for (int p = 0; p < 2; p++) {
                uint32_t Bh[4], Bl[4];
                ldsm4t(Bh, vHi + vkb + p * 32);
                ldsm4t(Bl, vLo + vkb + p * 32);
                mma_bf16(acc[0][2*p],   Ah[0], Bh[0], Bh[1]);
                mma_bf16(acc[1][2*p],   Ah[1], Bh[0], Bh[1]);
                mma_bf16(acc[0][2*p],   Ah[0], Bl[0], Bl[1]);
                mma_bf16(acc[1][2*p],   Ah[1], Bl[0], Bl[1]);
                mma_bf16(acc[0][2*p],   Al[0], Bh[0], Bh[1]);
                mma_bf16(acc[1][2*p],   Al[1], Bh[0], Bh[1]);
                mma_bf16(acc[0][2*p+1], Ah[0], Bh[2], Bh[3]);
                mma_bf16(acc[1][2*p+1], Ah[1], Bh[2], Bh[3]);
                mma_bf16(acc[0][2*p+1], Ah[0], Bl[2], Bl[3]);
                mma_bf16(acc[1][2*p+1], Ah[1], Bl[2], Bl[3]);
                mma_bf16(acc[0][2*p+1], Al[0], Bh[2], Bh[3]);
                mma_bf16(acc[1][2*p+1], Al[1], Bh[2], Bh[3]);
            }
        }
        __syncthreads();
    }

    #pragma unroll
    for (int m = 0; m < 2; m++) {
        int gq = q0 + wq * 32 + m * 16 + g;
        #pragma unroll
        for (int n = 0; n < 4; n++) {
            int gd = wd * 32 + n * 8 + tg * 2;
            *reinterpret_cast<float2*>(&ob[(size_t)gq * D + gd]) =
                make_float2(acc[m][n][0], acc[m][n][1]);
            *reinterpret_cast<float2*>(&ob[(size_t)(gq + 8) * D + gd]) =
                make_float2(acc[m][n][2], acc[m][n][3]);
        }
    }
}

// ===========================================================================
// launch: d_in = { q, k, v, mask } ; d_out = [ out | attn ]
// ===========================================================================
extern "C" void kernel_launch(void* const* d_in, const int* in_sizes, int n_in,
                              void* d_out, int out_size)
{
    const float* q = (const float*)d_in[0];
    const float* k = (const float*)d_in[1];
    const float* v = (const float*)d_in[2];

    float* out  = (float*)d_out;
    float* attn = out + (size_t)BH * S * D;

    static bool configured = false;
    if (!configured) {
        cudaFuncSetAttribute(k_scores_mma, cudaFuncAttributeMaxDynamicSharedMemorySize, K1_SMEM);
        cudaFuncSetAttribute(k_av_mma,     cudaFuncAttributeMaxDynamicSharedMemorySize, K3_SMEM);
        configured = true;
    }

    k_scores_mma<<<dim3(16, 16, BH), 256, K1_SMEM>>>(q, k, attn);
    k_softmax   <<<BH * S, 128>>>(attn);
    k_av_mma    <<<dim3(16, BH), 256, K3_SMEM>>>(attn, v, out);
}